// round 5
// baseline (speedup 1.0000x reference)
#include <cuda_runtime.h>
#include <cuda_bf16.h>
#include <mma.h>
#include <cstdint>

using namespace nvcuda;
typedef __nv_bfloat16 bf16;

#define BATCH 64
#define TT    256
#define HHH   1024
#define GGG   4096
#define MTOT  (BATCH*TT)   // 16384

// ----------------------------------------------------------------------------
// Device-global scratch (allocation-free; ~437 MB total)
// ----------------------------------------------------------------------------
__device__ __align__(16) bf16  g_wih_hi[3][GGG*HHH];
__device__ __align__(16) bf16  g_wih_lo[3][GGG*HHH];
__device__ __align__(16) bf16  g_whh_hi[3][GGG*HHH];
__device__ __align__(16) bf16  g_whh_lo[3][GGG*HHH];
__device__            float g_bias[3][GGG];
__device__ __align__(16) float g_xg[(size_t)MTOT*GGG];    // 268 MB; permuted gate cols (NO bias)
__device__ __align__(16) bf16  g_in_hi[(size_t)MTOT*HHH]; // layer input (hi part)
__device__ __align__(16) bf16  g_in_lo[(size_t)MTOT*HHH]; // layer input (lo part)
__device__ __align__(16) bf16  g_h_hi[2][BATCH*HHH];      // double-buffered hidden
__device__ __align__(16) bf16  g_h_lo[2][BATCH*HHH];
__device__            float g_c[BATCH*HHH];
__device__            float g_hlast[BATCH*HHH];           // final h of last layer (fp32)

// Gate-row permutation: permuted row cp -> original row of [4H, K] weight.
// Block of 32 permuted rows = (i,f,g,o) x 8 h-indices for h in [8*nb, 8*nb+8).
__device__ __forceinline__ int perm_row(int cp) {
    int nb = cp >> 5, r = cp & 31;
    return (r >> 3) * HHH + nb * 8 + (r & 7);
}

// ----------------------------------------------------------------------------
// Prep: split fp32 weights into bf16 hi/lo with gate-row permutation
// ----------------------------------------------------------------------------
__global__ void prep_w_kernel(const float* __restrict__ w, int l, int which, int cols) {
    size_t idx = (size_t)blockIdx.x * blockDim.x + threadIdx.x;
    size_t n = (size_t)GGG * cols;
    if (idx >= n) return;
    int rp = (int)(idx / cols), c = (int)(idx % cols);
    int r = perm_row(rp);
    float v = w[(size_t)r * cols + c];
    bf16 hi = __float2bfloat16(v);
    bf16 lo = __float2bfloat16(v - __bfloat162float(hi));
    if (which == 0) { g_wih_hi[l][idx] = hi; g_wih_lo[l][idx] = lo; }
    else            { g_whh_hi[l][idx] = hi; g_whh_lo[l][idx] = lo; }
}

__global__ void prep_bias_kernel(const float* __restrict__ bih,
                                 const float* __restrict__ bhh, int l) {
    int cp = blockIdx.x * blockDim.x + threadIdx.x;
    if (cp < GGG) { int r = perm_row(cp); g_bias[l][cp] = bih[r] + bhh[r]; }
}

// Split external input x into bf16 hi/lo (layer 0 only)
__global__ void split_x_kernel(const float* __restrict__ x, size_t n) {
    size_t i = (size_t)blockIdx.x * blockDim.x + threadIdx.x;
    if (i >= n) return;
    float v = x[i];
    bf16 hi = __float2bfloat16(v);
    g_in_hi[i] = hi;
    g_in_lo[i] = __float2bfloat16(v - __bfloat162float(hi));
}

__global__ void init_state_kernel() {
    int i = blockIdx.x * blockDim.x + threadIdx.x;  // 65536 total
    g_c[i] = 0.f;
    g_h_hi[0][i] = __float2bfloat16(0.f);
    g_h_lo[0][i] = __float2bfloat16(0.f);
}

// ----------------------------------------------------------------------------
// xg GEMM: g_xg[M=16384, N=4096] = (Ah+Al)[M,K] @ (Bh+Bl)[N,K]^T (x3 split MMA)
// Block tile 128x128, 8 warps (2x4), warp tile 64x32.
// Accumulators stored DIRECTLY to global (ldm=GGG); bias added in step kernel.
// ----------------------------------------------------------------------------
__global__ void xg_gemm_kernel(int l, int K) {
    __shared__ __align__(32) bf16 sAh[128][24], sAl[128][24], sBh[128][24], sBl[128][24];
    int m0 = blockIdx.y * 128, n0 = blockIdx.x * 128;
    int tid = threadIdx.x, warp = tid >> 5;
    int wm = warp >> 2, wn = warp & 3;   // 2 x 4 warp grid

    wmma::fragment<wmma::accumulator, 16, 16, 16, float> acc[4][2];
#pragma unroll
    for (int i = 0; i < 4; i++)
#pragma unroll
        for (int j = 0; j < 2; j++) wmma::fill_fragment(acc[i][j], 0.f);

    const bf16* Ah = g_in_hi;       const bf16* Al = g_in_lo;
    const bf16* Bh = g_wih_hi[l];   const bf16* Bl = g_wih_lo[l];

    int r = tid >> 1, c8 = (tid & 1) * 8;
    for (int k0 = 0; k0 < K; k0 += 16) {
        *(uint4*)&sAh[r][c8] = *(const uint4*)&Ah[(size_t)(m0 + r) * K + k0 + c8];
        *(uint4*)&sAl[r][c8] = *(const uint4*)&Al[(size_t)(m0 + r) * K + k0 + c8];
        *(uint4*)&sBh[r][c8] = *(const uint4*)&Bh[(size_t)(n0 + r) * K + k0 + c8];
        *(uint4*)&sBl[r][c8] = *(const uint4*)&Bl[(size_t)(n0 + r) * K + k0 + c8];
        __syncthreads();

        wmma::fragment<wmma::matrix_a, 16, 16, 16, bf16, wmma::row_major> ah[4], al[4];
        wmma::fragment<wmma::matrix_b, 16, 16, 16, bf16, wmma::col_major> bh[2], bl[2];
#pragma unroll
        for (int i = 0; i < 4; i++) {
            wmma::load_matrix_sync(ah[i], &sAh[wm * 64 + i * 16][0], 24);
            wmma::load_matrix_sync(al[i], &sAl[wm * 64 + i * 16][0], 24);
        }
#pragma unroll
        for (int j = 0; j < 2; j++) {
            wmma::load_matrix_sync(bh[j], &sBh[wn * 32 + j * 16][0], 24);
            wmma::load_matrix_sync(bl[j], &sBl[wn * 32 + j * 16][0], 24);
        }
#pragma unroll
        for (int i = 0; i < 4; i++)
#pragma unroll
            for (int j = 0; j < 2; j++) {
                wmma::mma_sync(acc[i][j], ah[i], bh[j], acc[i][j]);
                wmma::mma_sync(acc[i][j], ah[i], bl[j], acc[i][j]);
                wmma::mma_sync(acc[i][j], al[i], bh[j], acc[i][j]);
            }
        __syncthreads();
    }
    // Direct global store (ldm = GGG = 4096, multiple of 4; 64B-aligned cols)
#pragma unroll
    for (int i = 0; i < 4; i++)
#pragma unroll
        for (int j = 0; j < 2; j++) {
            size_t row = (size_t)(m0 + wm * 64 + i * 16);
            int col = n0 + wn * 32 + j * 16;
            wmma::store_matrix_sync(&g_xg[row * GGG + col], acc[i][j], GGG,
                                    wmma::mem_row_major);
        }
}

// ----------------------------------------------------------------------------
// Recurrence step: one launch per t. 128 blocks; block nb owns h in [8nb, 8nb+8)
// (all 4 gates via permuted weight rows [32nb, 32nb+32)).
// gates[64 x 32] = (Hh+Hl)[64,1024] @ Whh'[32,1024]^T (x3), then fused LSTM cell.
// Bias (32 floats) cached in smem. Writes next-layer input directly.
// ----------------------------------------------------------------------------
__global__ void step_kernel(int l, int t) {
    __shared__ __align__(32) bf16 sAh[64][40], sAl[64][40], sBh[32][40], sBl[32][40];
    __shared__ __align__(32) float sg[64][36];   // 64x32 tile + pad (ldm 36, mult of 4)
    __shared__ float sbias[32];
    int nb = blockIdx.x;
    int tid = threadIdx.x, warp = tid >> 5;
    int rp = t & 1, wp = rp ^ 1;

    if (tid < 32) sbias[tid] = g_bias[l][nb * 32 + tid];

    const bf16* Ah = g_h_hi[rp];
    const bf16* Al = g_h_lo[rp];
    const bf16* Bh = &g_whh_hi[l][(size_t)(nb * 32) * HHH];
    const bf16* Bl = &g_whh_lo[l][(size_t)(nb * 32) * HHH];

    wmma::fragment<wmma::accumulator, 16, 16, 16, float> acc[2];
    wmma::fill_fragment(acc[0], 0.f);
    wmma::fill_fragment(acc[1], 0.f);

    int ar = tid >> 1, ac = (tid & 1) * 16;
    int br = (tid & 63) >> 1, bc = ((tid & 63) & 1) * 16;

    for (int k0 = 0; k0 < HHH; k0 += 32) {
        *(uint4*)&sAh[ar][ac]     = *(const uint4*)&Ah[(size_t)ar * HHH + k0 + ac];
        *(uint4*)&sAh[ar][ac + 8] = *(const uint4*)&Ah[(size_t)ar * HHH + k0 + ac + 8];
        *(uint4*)&sAl[ar][ac]     = *(const uint4*)&Al[(size_t)ar * HHH + k0 + ac];
        *(uint4*)&sAl[ar][ac + 8] = *(const uint4*)&Al[(size_t)ar * HHH + k0 + ac + 8];
        if (tid < 64) {
            *(uint4*)&sBh[br][bc]     = *(const uint4*)&Bh[(size_t)br * HHH + k0 + bc];
            *(uint4*)&sBh[br][bc + 8] = *(const uint4*)&Bh[(size_t)br * HHH + k0 + bc + 8];
        } else {
            *(uint4*)&sBl[br][bc]     = *(const uint4*)&Bl[(size_t)br * HHH + k0 + bc];
            *(uint4*)&sBl[br][bc + 8] = *(const uint4*)&Bl[(size_t)br * HHH + k0 + bc + 8];
        }
        __syncthreads();

#pragma unroll
        for (int ks = 0; ks < 2; ks++) {
            wmma::fragment<wmma::matrix_a, 16, 16, 16, bf16, wmma::row_major> a_h, a_l;
            wmma::fragment<wmma::matrix_b, 16, 16, 16, bf16, wmma::col_major> b_h[2], b_l[2];
            wmma::load_matrix_sync(a_h, &sAh[warp * 16][ks * 16], 40);
            wmma::load_matrix_sync(a_l, &sAl[warp * 16][ks * 16], 40);
#pragma unroll
            for (int j = 0; j < 2; j++) {
                wmma::load_matrix_sync(b_h[j], &sBh[j * 16][ks * 16], 40);
                wmma::load_matrix_sync(b_l[j], &sBl[j * 16][ks * 16], 40);
            }
#pragma unroll
            for (int j = 0; j < 2; j++) {
                wmma::mma_sync(acc[j], a_h, b_h[j], acc[j]);
                wmma::mma_sync(acc[j], a_h, b_l[j], acc[j]);
                wmma::mma_sync(acc[j], a_l, b_h[j], acc[j]);
            }
        }
        __syncthreads();
    }
#pragma unroll
    for (int j = 0; j < 2; j++)
        wmma::store_matrix_sync(&sg[warp * 16][j * 16], acc[j], 36, wmma::mem_row_major);
    __syncthreads();

    // Fused LSTM cell update: 512 (b, hh) pairs over 128 threads
    for (int q = tid; q < 512; q += 128) {
        int b = q >> 3, hh = q & 7;
        int m = b * TT + t;
        size_t xoff = (size_t)m * GGG + nb * 32;
        float iv = sg[b][hh]      + g_xg[xoff + hh]      + sbias[hh];
        float fv = sg[b][8 + hh]  + g_xg[xoff + 8 + hh]  + sbias[8 + hh];
        float gv = sg[b][16 + hh] + g_xg[xoff + 16 + hh] + sbias[16 + hh];
        float ov = sg[b][24 + hh] + g_xg[xoff + 24 + hh] + sbias[24 + hh];
        int h = nb * 8 + hh;
        float cprev = g_c[b * HHH + h];
        float ig = 1.f / (1.f + expf(-iv));
        float fg = 1.f / (1.f + expf(-fv));
        float og = 1.f / (1.f + expf(-ov));
        float gt = tanhf(gv);
        float cn = fg * cprev + ig * gt;
        float hn = og * tanhf(cn);
        g_c[b * HHH + h] = cn;
        bf16 hi = __float2bfloat16(hn);
        bf16 lo = __float2bfloat16(hn - __bfloat162float(hi));
        g_h_hi[wp][b * HHH + h] = hi;
        g_h_lo[wp][b * HHH + h] = lo;
        // Next-layer input (current layer's xg GEMM already consumed g_in)
        g_in_hi[(size_t)m * HHH + h] = hi;
        g_in_lo[(size_t)m * HHH + h] = lo;
        if (l == 2 && t == TT - 1) g_hlast[b * HHH + h] = hn;
    }
}

// ----------------------------------------------------------------------------
// Final FC: out[b] = hlast[b, :] . fc_w + fc_b   (D_OUT = 1)
// ----------------------------------------------------------------------------
__global__ void fc_kernel(const float* __restrict__ fw, const float* __restrict__ fb,
                          float* __restrict__ out) {
    int b = blockIdx.x, tid = threadIdx.x;
    __shared__ float red[256];
    const float* hrow = &g_hlast[b * HHH];
    float s = 0.f;
    for (int h = tid; h < HHH; h += 256) s += hrow[h] * fw[h];
    red[tid] = s;
    __syncthreads();
    for (int off = 128; off; off >>= 1) {
        if (tid < off) red[tid] += red[tid + off];
        __syncthreads();
    }
    if (tid == 0) out[b] = red[0] + fb[0];
}

// ----------------------------------------------------------------------------
// Launch
// ----------------------------------------------------------------------------
extern "C" void kernel_launch(void* const* d_in, const int* in_sizes, int n_in,
                              void* d_out, int out_size) {
    const float* x = (const float*)d_in[0];

    // Weight/bias prep (cheap, deterministic)
    for (int l = 0; l < 3; l++) {
        int cols = (l == 0) ? 256 : 1024;
        size_t nih = (size_t)GGG * cols;
        prep_w_kernel<<<(unsigned)((nih + 255) / 256), 256>>>(
            (const float*)d_in[1 + 4 * l], l, 0, cols);
        prep_w_kernel<<<(GGG * HHH + 255) / 256, 256>>>(
            (const float*)d_in[2 + 4 * l], l, 1, HHH);
        prep_bias_kernel<<<16, 256>>>(
            (const float*)d_in[3 + 4 * l], (const float*)d_in[4 + 4 * l], l);
    }

    // Layer-0 input split
    split_x_kernel<<<(MTOT * 256 + 255) / 256, 256>>>(x, (size_t)MTOT * 256);

    for (int l = 0; l < 3; l++) {
        int K = (l == 0) ? 256 : 1024;
        dim3 grid(GGG / 128, MTOT / 128);
        xg_gemm_kernel<<<grid, 256>>>(l, K);
        init_state_kernel<<<256, 256>>>();
        for (int t = 0; t < TT; t++) step_kernel<<<128, 128>>>(l, t);
    }
    fc_kernel<<<BATCH, 256>>>((const float*)d_in[13], (const float*)d_in[14],
                              (float*)d_out);
}

// round 7
// speedup vs baseline: 1.7608x; 1.7608x over previous
#include <cuda_runtime.h>
#include <cuda_bf16.h>
#include <mma.h>
#include <cstdint>

using namespace nvcuda;
typedef __nv_bfloat16 bf16;

#define BATCH 64
#define TT    256
#define HHH   1024
#define GGG   4096
#define MTOT  (BATCH*TT)   // 16384

#define NBLK  128
#define NTHR  256
#define WLD   1032         // weight smem row stride (bf16 elems), mult of 8
#define ALD   72           // A-tile smem row stride
#define AMAT  (64*ALD)     // 4608 elems per A matrix

// Dynamic smem layout (bytes):
//   sWh: 32*WLD*2        = 66048
//   sWl: 32*WLD*2        = 66048
//   sA : 4 * AMAT * 2    = 36864   (buf0{hi,lo}, buf1{hi,lo})
//   sg : 64*36*4         = 9216
//   sbias: 32*4          = 128
#define SMEM_TOTAL (66048*2 + 36864 + 9216 + 128)

// ----------------------------------------------------------------------------
// Device-global scratch (allocation-free)
// ----------------------------------------------------------------------------
__device__ __align__(16) bf16  g_wih_hi[3][GGG*HHH];
__device__ __align__(16) bf16  g_wih_lo[3][GGG*HHH];
__device__ __align__(16) bf16  g_whh_hi[3][GGG*HHH];
__device__ __align__(16) bf16  g_whh_lo[3][GGG*HHH];
__device__            float g_bias[3][GGG];
__device__ __align__(16) float g_xg[(size_t)MTOT*GGG];    // 268 MB; permuted gate cols (NO bias)
__device__ __align__(16) bf16  g_in_hi[(size_t)MTOT*HHH]; // layer input (hi part)
__device__ __align__(16) bf16  g_in_lo[(size_t)MTOT*HHH]; // layer input (lo part)
__device__ __align__(16) bf16  g_h_hi[2][BATCH*HHH];      // double-buffered hidden
__device__ __align__(16) bf16  g_h_lo[2][BATCH*HHH];
__device__            float g_hlast[BATCH*HHH];           // final h of last layer (fp32)
__device__            unsigned g_bar;                     // grid barrier counter

// Gate-row permutation: permuted row cp -> original row of [4H, K] weight.
// Block of 32 permuted rows = (i,f,g,o) x 8 h-indices for h in [8*nb, 8*nb+8).
__device__ __forceinline__ int perm_row(int cp) {
    int nb = cp >> 5, r = cp & 31;
    return (r >> 3) * HHH + nb * 8 + (r & 7);
}

__device__ __forceinline__ float fsig(float x) {
    return 1.f / (1.f + __expf(-x));
}
__device__ __forceinline__ float ftanh(float x) {
    // tanh via exp: 1 - 2/(e^{2x}+1); accurate to ~1e-7 rel with __expf
    return 1.f - 2.f / (__expf(2.f * x) + 1.f);
}

// ----------------------------------------------------------------------------
// Prep kernels
// ----------------------------------------------------------------------------
__global__ void prep_w_kernel(const float* __restrict__ w, int l, int which, int cols) {
    size_t idx = (size_t)blockIdx.x * blockDim.x + threadIdx.x;
    size_t n = (size_t)GGG * cols;
    if (idx >= n) return;
    int rp = (int)(idx / cols), c = (int)(idx % cols);
    int r = perm_row(rp);
    float v = w[(size_t)r * cols + c];
    bf16 hi = __float2bfloat16(v);
    bf16 lo = __float2bfloat16(v - __bfloat162float(hi));
    if (which == 0) { g_wih_hi[l][idx] = hi; g_wih_lo[l][idx] = lo; }
    else            { g_whh_hi[l][idx] = hi; g_whh_lo[l][idx] = lo; }
}

__global__ void prep_bias_kernel(const float* __restrict__ bih,
                                 const float* __restrict__ bhh, int l) {
    int cp = blockIdx.x * blockDim.x + threadIdx.x;
    if (cp < GGG) { int r = perm_row(cp); g_bias[l][cp] = bih[r] + bhh[r]; }
}

__global__ void split_x_kernel(const float* __restrict__ x, size_t n) {
    size_t i = (size_t)blockIdx.x * blockDim.x + threadIdx.x;
    if (i >= n) return;
    float v = x[i];
    bf16 hi = __float2bfloat16(v);
    g_in_hi[i] = hi;
    g_in_lo[i] = __float2bfloat16(v - __bfloat162float(hi));
}

__global__ void init_state_kernel() {
    int i = blockIdx.x * blockDim.x + threadIdx.x;  // 65536 total
    g_h_hi[0][i] = __float2bfloat16(0.f);
    g_h_lo[0][i] = __float2bfloat16(0.f);
    if (i == 0) g_bar = 0u;
}

// ----------------------------------------------------------------------------
// xg GEMM: g_xg[M,4096] = (Ah+Al)[M,K] @ (Bh+Bl)[4096,K]^T (x3 split MMA)
// Block tile 128x128, 8 warps, warp tile 64x32. Direct global stores.
// ----------------------------------------------------------------------------
__global__ void xg_gemm_kernel(int l, int K) {
    __shared__ __align__(32) bf16 sAh[128][24], sAl[128][24], sBh[128][24], sBl[128][24];
    int m0 = blockIdx.y * 128, n0 = blockIdx.x * 128;
    int tid = threadIdx.x, warp = tid >> 5;
    int wm = warp >> 2, wn = warp & 3;

    wmma::fragment<wmma::accumulator, 16, 16, 16, float> acc[4][2];
#pragma unroll
    for (int i = 0; i < 4; i++)
#pragma unroll
        for (int j = 0; j < 2; j++) wmma::fill_fragment(acc[i][j], 0.f);

    const bf16* Ah = g_in_hi;       const bf16* Al = g_in_lo;
    const bf16* Bh = g_wih_hi[l];   const bf16* Bl = g_wih_lo[l];

    int r = tid >> 1, c8 = (tid & 1) * 8;
    for (int k0 = 0; k0 < K; k0 += 16) {
        *(uint4*)&sAh[r][c8] = *(const uint4*)&Ah[(size_t)(m0 + r) * K + k0 + c8];
        *(uint4*)&sAl[r][c8] = *(const uint4*)&Al[(size_t)(m0 + r) * K + k0 + c8];
        *(uint4*)&sBh[r][c8] = *(const uint4*)&Bh[(size_t)(n0 + r) * K + k0 + c8];
        *(uint4*)&sBl[r][c8] = *(const uint4*)&Bl[(size_t)(n0 + r) * K + k0 + c8];
        __syncthreads();

        wmma::fragment<wmma::matrix_a, 16, 16, 16, bf16, wmma::row_major> ah[4], al[4];
        wmma::fragment<wmma::matrix_b, 16, 16, 16, bf16, wmma::col_major> bh[2], bl[2];
#pragma unroll
        for (int i = 0; i < 4; i++) {
            wmma::load_matrix_sync(ah[i], &sAh[wm * 64 + i * 16][0], 24);
            wmma::load_matrix_sync(al[i], &sAl[wm * 64 + i * 16][0], 24);
        }
#pragma unroll
        for (int j = 0; j < 2; j++) {
            wmma::load_matrix_sync(bh[j], &sBh[wn * 32 + j * 16][0], 24);
            wmma::load_matrix_sync(bl[j], &sBl[wn * 32 + j * 16][0], 24);
        }
#pragma unroll
        for (int i = 0; i < 4; i++)
#pragma unroll
            for (int j = 0; j < 2; j++) {
                wmma::mma_sync(acc[i][j], ah[i], bh[j], acc[i][j]);
                wmma::mma_sync(acc[i][j], ah[i], bl[j], acc[i][j]);
                wmma::mma_sync(acc[i][j], al[i], bh[j], acc[i][j]);
            }
        __syncthreads();
    }
#pragma unroll
    for (int i = 0; i < 4; i++)
#pragma unroll
        for (int j = 0; j < 2; j++) {
            size_t row = (size_t)(m0 + wm * 64 + i * 16);
            int col = n0 + wn * 32 + j * 16;
            wmma::store_matrix_sync(&g_xg[row * GGG + col], acc[i][j], GGG,
                                    wmma::mem_row_major);
        }
}

// ----------------------------------------------------------------------------
// Persistent recurrence kernel: one launch per LAYER (grid=128, co-resident).
// Block nb owns permuted gate rows [32nb,32nb+32) => h slice [8nb, 8nb+8).
// Whh slice (hi+lo) cached in smem for all 256 timesteps. c in registers.
// Grid barrier: atomic counter + volatile poll (128 blocks <= 148 SMs).
// ----------------------------------------------------------------------------
__global__ void __launch_bounds__(NTHR, 1) layer_kernel(int l) {
    extern __shared__ __align__(16) char smem_raw[];
    bf16*  sWh   = (bf16*)smem_raw;               // [32][WLD]
    bf16*  sWl   = sWh + 32 * WLD;
    bf16*  sA    = sWl + 32 * WLD;                // [2 bufs][hi,lo][64][ALD]
    float* sg    = (float*)(sA + 4 * AMAT);       // [64][36]
    float* sbias = sg + 64 * 36;                  // [32]

    int nb = blockIdx.x;
    int tid = threadIdx.x, warp = tid >> 5;
    int wm = warp >> 1, wn = warp & 1;            // 4x2 warp grid over 64x32 tile

    // --- Load Whh slice into smem (once per layer) ---
    {
        const bf16* Bh = &g_whh_hi[l][(size_t)(nb * 32) * HHH];
        const bf16* Bl = &g_whh_lo[l][(size_t)(nb * 32) * HHH];
        for (int i = tid; i < 32 * 128; i += NTHR) {      // 128 uint4 per row
            int r = i >> 7, c = (i & 127) * 8;
            *(uint4*)&sWh[r * WLD + c] = *(const uint4*)&Bh[(size_t)r * HHH + c];
            *(uint4*)&sWl[r * WLD + c] = *(const uint4*)&Bl[(size_t)r * HHH + c];
        }
        if (tid < 32) sbias[tid] = g_bias[l][nb * 32 + tid];
    }
    __syncthreads();

    // Cell state in registers: thread owns (b=tid>>2, hh2=(tid&3)*2) and hh2+1
    int bq = tid >> 2;
    int hh2 = (tid & 3) * 2;
    float c0 = 0.f, c1 = 0.f;

    wmma::fragment<wmma::accumulator, 16, 16, 16, float> acc;

    for (int t = 0; t < TT; t++) {
        int rp = t & 1, wp = rp ^ 1;
        const bf16* Ah = g_h_hi[rp];
        const bf16* Al = g_h_lo[rp];

        // Prefetch xg tile values for this thread (latency hidden by k-loop)
        size_t xbase = ((size_t)bq * TT + t) * GGG + nb * 32;
        float2 x0 = *(const float2*)&g_xg[xbase + hh2];
        float2 x1 = *(const float2*)&g_xg[xbase + 8 + hh2];
        float2 x2 = *(const float2*)&g_xg[xbase + 16 + hh2];
        float2 x3 = *(const float2*)&g_xg[xbase + 24 + hh2];

        wmma::fill_fragment(acc, 0.f);

        // k-loop: 16 chunks of 64, double-buffered A
        {
            // prologue: chunk 0 -> buf 0
#pragma unroll
            for (int u = 0; u < 2; u++) {
                int idx = tid + u * NTHR;          // 0..511
                int r = idx >> 3, c = (idx & 7) * 8;
                *(uint4*)&sA[0 * AMAT + r * ALD + c] = *(const uint4*)&Ah[(size_t)r * HHH + c];
                *(uint4*)&sA[1 * AMAT + r * ALD + c] = *(const uint4*)&Al[(size_t)r * HHH + c];
            }
            __syncthreads();

            for (int ch = 0; ch < 16; ch++) {
                int cur = ch & 1;
                if (ch < 15) {
                    int nxt = cur ^ 1;
                    int k0n = (ch + 1) * 64;
#pragma unroll
                    for (int u = 0; u < 2; u++) {
                        int idx = tid + u * NTHR;
                        int r = idx >> 3, c = (idx & 7) * 8;
                        *(uint4*)&sA[(nxt * 2 + 0) * AMAT + r * ALD + c] =
                            *(const uint4*)&Ah[(size_t)r * HHH + k0n + c];
                        *(uint4*)&sA[(nxt * 2 + 1) * AMAT + r * ALD + c] =
                            *(const uint4*)&Al[(size_t)r * HHH + k0n + c];
                    }
                }
                const bf16* bufAh = sA + (cur * 2 + 0) * AMAT;
                const bf16* bufAl = sA + (cur * 2 + 1) * AMAT;
#pragma unroll
                for (int ks = 0; ks < 4; ks++) {
                    int kk = ks * 16;
                    wmma::fragment<wmma::matrix_a, 16, 16, 16, bf16, wmma::row_major> a_h, a_l;
                    wmma::fragment<wmma::matrix_b, 16, 16, 16, bf16, wmma::col_major> b_h, b_l;
                    wmma::load_matrix_sync(a_h, &bufAh[(wm * 16) * ALD + kk], ALD);
                    wmma::load_matrix_sync(a_l, &bufAl[(wm * 16) * ALD + kk], ALD);
                    wmma::load_matrix_sync(b_h, &sWh[(wn * 16) * WLD + ch * 64 + kk], WLD);
                    wmma::load_matrix_sync(b_l, &sWl[(wn * 16) * WLD + ch * 64 + kk], WLD);
                    wmma::mma_sync(acc, a_h, b_h, acc);
                    wmma::mma_sync(acc, a_h, b_l, acc);
                    wmma::mma_sync(acc, a_l, b_h, acc);
                }
                __syncthreads();
            }
        }

        // Stage gates to smem
        wmma::store_matrix_sync(&sg[(wm * 16) * 36 + wn * 16], acc, 36, wmma::mem_row_major);
        __syncthreads();

        // Fused LSTM cell update (2 (b,hh) pairs per thread)
        {
            float iv0 = sg[bq * 36 + hh2]          + x0.x + sbias[hh2];
            float iv1 = sg[bq * 36 + hh2 + 1]      + x0.y + sbias[hh2 + 1];
            float fv0 = sg[bq * 36 + 8 + hh2]      + x1.x + sbias[8 + hh2];
            float fv1 = sg[bq * 36 + 8 + hh2 + 1]  + x1.y + sbias[8 + hh2 + 1];
            float gv0 = sg[bq * 36 + 16 + hh2]     + x2.x + sbias[16 + hh2];
            float gv1 = sg[bq * 36 + 16 + hh2 + 1] + x2.y + sbias[16 + hh2 + 1];
            float ov0 = sg[bq * 36 + 24 + hh2]     + x3.x + sbias[24 + hh2];
            float ov1 = sg[bq * 36 + 24 + hh2 + 1] + x3.y + sbias[24 + hh2 + 1];

            c0 = fsig(fv0) * c0 + fsig(iv0) * ftanh(gv0);
            c1 = fsig(fv1) * c1 + fsig(iv1) * ftanh(gv1);
            float h0 = fsig(ov0) * ftanh(c0);
            float h1 = fsig(ov1) * ftanh(c1);

            int hidx = nb * 8 + hh2;
            bf16 h0_hi = __float2bfloat16(h0);
            bf16 h1_hi = __float2bfloat16(h1);
            bf16 h0_lo = __float2bfloat16(h0 - __bfloat162float(h0_hi));
            bf16 h1_lo = __float2bfloat16(h1 - __bfloat162float(h1_hi));
            __nv_bfloat162 phi; phi.x = h0_hi; phi.y = h1_hi;
            __nv_bfloat162 plo; plo.x = h0_lo; plo.y = h1_lo;

            *(__nv_bfloat162*)&g_h_hi[wp][bq * HHH + hidx] = phi;
            *(__nv_bfloat162*)&g_h_lo[wp][bq * HHH + hidx] = plo;
            if (l < 2) {
                size_t m = (size_t)bq * TT + t;
                *(__nv_bfloat162*)&g_in_hi[m * HHH + hidx] = phi;
                *(__nv_bfloat162*)&g_in_lo[m * HHH + hidx] = plo;
            }
            if (l == 2 && t == TT - 1) {
                g_hlast[bq * HHH + hidx]     = h0;
                g_hlast[bq * HHH + hidx + 1] = h1;
            }
        }

        // Grid barrier (skip after last step)
        if (t < TT - 1) {
            __threadfence();
            __syncthreads();
            if (tid == 0) {
                atomicAdd(&g_bar, 1u);
                unsigned want = (unsigned)(t + 1) * NBLK;
                volatile unsigned* p = &g_bar;
                while (*p < want) { }
                __threadfence();
            }
            __syncthreads();
        }
    }
}

// ----------------------------------------------------------------------------
// Final FC: out[b] = hlast[b, :] . fc_w + fc_b   (D_OUT = 1)
// ----------------------------------------------------------------------------
__global__ void fc_kernel(const float* __restrict__ fw, const float* __restrict__ fb,
                          float* __restrict__ out) {
    int b = blockIdx.x, tid = threadIdx.x;
    __shared__ float red[256];
    const float* hrow = &g_hlast[b * HHH];
    float s = 0.f;
    for (int h = tid; h < HHH; h += 256) s += hrow[h] * fw[h];
    red[tid] = s;
    __syncthreads();
    for (int off = 128; off; off >>= 1) {
        if (tid < off) red[tid] += red[tid + off];
        __syncthreads();
    }
    if (tid == 0) out[b] = red[0] + fb[0];
}

// ----------------------------------------------------------------------------
// Launch
// ----------------------------------------------------------------------------
extern "C" void kernel_launch(void* const* d_in, const int* in_sizes, int n_in,
                              void* d_out, int out_size) {
    const float* x = (const float*)d_in[0];

    cudaFuncSetAttribute(layer_kernel, cudaFuncAttributeMaxDynamicSharedMemorySize,
                         SMEM_TOTAL);

    for (int l = 0; l < 3; l++) {
        int cols = (l == 0) ? 256 : 1024;
        size_t nih = (size_t)GGG * cols;
        prep_w_kernel<<<(unsigned)((nih + 255) / 256), 256>>>(
            (const float*)d_in[1 + 4 * l], l, 0, cols);
        prep_w_kernel<<<(GGG * HHH + 255) / 256, 256>>>(
            (const float*)d_in[2 + 4 * l], l, 1, HHH);
        prep_bias_kernel<<<16, 256>>>(
            (const float*)d_in[3 + 4 * l], (const float*)d_in[4 + 4 * l], l);
    }

    split_x_kernel<<<(MTOT * 256 + 255) / 256, 256>>>(x, (size_t)MTOT * 256);

    for (int l = 0; l < 3; l++) {
        int K = (l == 0) ? 256 : 1024;
        dim3 grid(GGG / 128, MTOT / 128);
        xg_gemm_kernel<<<grid, 256>>>(l, K);
        init_state_kernel<<<256, 256>>>();
        layer_kernel<<<NBLK, NTHR, SMEM_TOTAL>>>(l);
    }
    fc_kernel<<<BATCH, 256>>>((const float*)d_in[13], (const float*)d_in[14],
                              (float*)d_out);
}

// round 8
// speedup vs baseline: 4.0666x; 2.3095x over previous
#include <cuda_runtime.h>
#include <cuda_fp16.h>
#include <mma.h>
#include <cstdint>

using namespace nvcuda;

#define BATCH 64
#define TT    256
#define HHH   1024
#define GGG   4096
#define MTOT  (BATCH*TT)   // 16384

#define NBLK  128
#define NTHR  256
#define WLD   1032         // weight smem row stride (half elems), mult of 8
#define CHUNK 512
#define ALD   520          // A-tile smem row stride (half elems), mult of 8
#define ABUF  (64*ALD)     // halfs per A buffer

// Dynamic smem: 32*WLD*2 + 2*ABUF*2 + 64*36*4 + 32*4 = 66048+133120+9216+128
#define SMEM_TOTAL (66048 + 133120 + 9216 + 128)

// ----------------------------------------------------------------------------
// Device-global scratch (allocation-free)
// ----------------------------------------------------------------------------
__device__ __align__(16) half  g_wih[3][GGG*HHH];
__device__ __align__(16) half  g_whh[3][GGG*HHH];
__device__            float g_bias[3][GGG];
__device__ __align__(16) float g_xg[(size_t)MTOT*GGG];    // 268 MB; permuted gate cols
__device__ __align__(16) half  g_in[(size_t)MTOT*HHH];    // layer input
__device__ __align__(16) half  g_h[2][BATCH*HHH];         // double-buffered hidden
__device__            float g_hlast[BATCH*HHH];           // final h of last layer (fp32)
__device__            unsigned g_bar;                     // grid barrier counter

// Gate-row permutation: permuted row cp -> original row of [4H, K] weight.
// Block of 32 permuted rows = (i,f,g,o) x 8 h-indices for h in [8*nb, 8*nb+8).
__device__ __forceinline__ int perm_row(int cp) {
    int nb = cp >> 5, r = cp & 31;
    return (r >> 3) * HHH + nb * 8 + (r & 7);
}

__device__ __forceinline__ float fsig(float x) {
    return 1.f / (1.f + __expf(-x));
}
__device__ __forceinline__ float ftanh(float x) {
    return 1.f - 2.f / (__expf(2.f * x) + 1.f);
}

// ----------------------------------------------------------------------------
// Prep kernels
// ----------------------------------------------------------------------------
__global__ void prep_w_kernel(const float* __restrict__ w, int l, int which, int cols) {
    size_t idx = (size_t)blockIdx.x * blockDim.x + threadIdx.x;
    size_t n = (size_t)GGG * cols;
    if (idx >= n) return;
    int rp = (int)(idx / cols), c = (int)(idx % cols);
    int r = perm_row(rp);
    float v = w[(size_t)r * cols + c];
    if (which == 0) g_wih[l][idx] = __float2half(v);
    else            g_whh[l][idx] = __float2half(v);
}

__global__ void prep_bias_kernel(const float* __restrict__ bih,
                                 const float* __restrict__ bhh, int l) {
    int cp = blockIdx.x * blockDim.x + threadIdx.x;
    if (cp < GGG) { int r = perm_row(cp); g_bias[l][cp] = bih[r] + bhh[r]; }
}

__global__ void split_x_kernel(const float* __restrict__ x, size_t n) {
    size_t i = (size_t)blockIdx.x * blockDim.x + threadIdx.x;
    if (i < n) g_in[i] = __float2half(x[i]);
}

__global__ void init_state_kernel() {
    int i = blockIdx.x * blockDim.x + threadIdx.x;  // 65536 total
    g_h[0][i] = __float2half(0.f);
    if (i == 0) g_bar = 0u;
}

// ----------------------------------------------------------------------------
// xg GEMM: g_xg[M,4096] = A[M,K](fp16) @ B[4096,K]^T(fp16), fp32 accum.
// Block tile 128x128, 8 warps (2x4), warp tile 64x32, k-chunk 32.
// ----------------------------------------------------------------------------
__global__ void xg_gemm_kernel(int l, int K) {
    __shared__ __align__(32) half sA[128][40], sB[128][40];
    int m0 = blockIdx.y * 128, n0 = blockIdx.x * 128;
    int tid = threadIdx.x, warp = tid >> 5;
    int wm = warp >> 2, wn = warp & 3;

    wmma::fragment<wmma::accumulator, 16, 16, 16, float> acc[4][2];
#pragma unroll
    for (int i = 0; i < 4; i++)
#pragma unroll
        for (int j = 0; j < 2; j++) wmma::fill_fragment(acc[i][j], 0.f);

    const half* A = g_in;
    const half* B = g_wih[l];

    int r = tid >> 1, c16 = (tid & 1) * 16;
    for (int k0 = 0; k0 < K; k0 += 32) {
        *(uint4*)&sA[r][c16]     = *(const uint4*)&A[(size_t)(m0 + r) * K + k0 + c16];
        *(uint4*)&sA[r][c16 + 8] = *(const uint4*)&A[(size_t)(m0 + r) * K + k0 + c16 + 8];
        *(uint4*)&sB[r][c16]     = *(const uint4*)&B[(size_t)(n0 + r) * K + k0 + c16];
        *(uint4*)&sB[r][c16 + 8] = *(const uint4*)&B[(size_t)(n0 + r) * K + k0 + c16 + 8];
        __syncthreads();

#pragma unroll
        for (int ks = 0; ks < 2; ks++) {
            wmma::fragment<wmma::matrix_a, 16, 16, 16, half, wmma::row_major> af[4];
            wmma::fragment<wmma::matrix_b, 16, 16, 16, half, wmma::col_major> bf[2];
#pragma unroll
            for (int i = 0; i < 4; i++)
                wmma::load_matrix_sync(af[i], &sA[wm * 64 + i * 16][ks * 16], 40);
#pragma unroll
            for (int j = 0; j < 2; j++)
                wmma::load_matrix_sync(bf[j], &sB[wn * 32 + j * 16][ks * 16], 40);
#pragma unroll
            for (int i = 0; i < 4; i++)
#pragma unroll
                for (int j = 0; j < 2; j++)
                    wmma::mma_sync(acc[i][j], af[i], bf[j], acc[i][j]);
        }
        __syncthreads();
    }
#pragma unroll
    for (int i = 0; i < 4; i++)
#pragma unroll
        for (int j = 0; j < 2; j++) {
            size_t row = (size_t)(m0 + wm * 64 + i * 16);
            int col = n0 + wn * 32 + j * 16;
            wmma::store_matrix_sync(&g_xg[row * GGG + col], acc[i][j], GGG,
                                    wmma::mem_row_major);
        }
}

// ----------------------------------------------------------------------------
// Persistent recurrence kernel: one launch per LAYER (grid=128, co-resident).
// Block nb owns permuted gate rows [32nb,32nb+32) => h slice [8nb, 8nb+8).
// Whh slice (fp16, 64KB) cached in smem for all 256 steps; c in registers.
// k-loop: 2 double-buffered chunks of 512.
// ----------------------------------------------------------------------------
__global__ void __launch_bounds__(NTHR, 1) layer_kernel(int l) {
    extern __shared__ __align__(16) char smem_raw[];
    half*  sW    = (half*)smem_raw;               // [32][WLD]
    half*  sA    = sW + 32 * WLD;                 // [2 bufs][64][ALD]
    float* sg    = (float*)(sA + 2 * ABUF);       // [64][36]
    float* sbias = sg + 64 * 36;                  // [32]

    int nb = blockIdx.x;
    int tid = threadIdx.x, warp = tid >> 5;
    int wm = warp >> 1, wn = warp & 1;            // 4x2 warps over 64x32 tile

    // --- Load Whh slice into smem (once per layer) ---
    {
        const half* Bw = &g_whh[l][(size_t)(nb * 32) * HHH];
        for (int i = tid; i < 32 * 128; i += NTHR) {      // 128 uint4 per row
            int r = i >> 7, c = (i & 127) * 8;
            *(uint4*)&sW[r * WLD + c] = *(const uint4*)&Bw[(size_t)r * HHH + c];
        }
        if (tid < 32) sbias[tid] = g_bias[l][nb * 32 + tid];
    }
    __syncthreads();

    // Cell state in registers: thread owns (b=tid>>2, hh2=(tid&3)*2) and hh2+1
    int bq = tid >> 2;
    int hh2 = (tid & 3) * 2;
    float c0 = 0.f, c1 = 0.f;

    wmma::fragment<wmma::accumulator, 16, 16, 16, float> acc;

    for (int t = 0; t < TT; t++) {
        int rp = t & 1, wp = rp ^ 1;
        const half* Ah = g_h[rp];

        // Prefetch xg tile values for this thread (latency hidden by k-loop)
        size_t xbase = ((size_t)bq * TT + t) * GGG + nb * 32;
        float2 x0 = *(const float2*)&g_xg[xbase + hh2];
        float2 x1 = *(const float2*)&g_xg[xbase + 8 + hh2];
        float2 x2 = *(const float2*)&g_xg[xbase + 16 + hh2];
        float2 x3 = *(const float2*)&g_xg[xbase + 24 + hh2];

        wmma::fill_fragment(acc, 0.f);

        // Prologue: chunk 0 -> buf 0  (64 rows x 512 halfs = 4096 uint4)
#pragma unroll
        for (int u = 0; u < 16; u++) {
            int idx = tid + u * NTHR;              // 0..4095
            int r = idx >> 6, c = (idx & 63) * 8;
            *(uint4*)&sA[0 * ABUF + r * ALD + c] = *(const uint4*)&Ah[(size_t)r * HHH + c];
        }
        __syncthreads();

#pragma unroll
        for (int ch = 0; ch < 2; ch++) {
            if (ch == 0) {
                // prefetch chunk 1 -> buf 1 (overlaps with chunk-0 MMAs)
#pragma unroll
                for (int u = 0; u < 16; u++) {
                    int idx = tid + u * NTHR;
                    int r = idx >> 6, c = (idx & 63) * 8;
                    *(uint4*)&sA[1 * ABUF + r * ALD + c] =
                        *(const uint4*)&Ah[(size_t)r * HHH + CHUNK + c];
                }
            }
            const half* bufA = sA + ch * ABUF;
#pragma unroll
            for (int ks = 0; ks < 32; ks++) {
                wmma::fragment<wmma::matrix_a, 16, 16, 16, half, wmma::row_major> af;
                wmma::fragment<wmma::matrix_b, 16, 16, 16, half, wmma::col_major> bf;
                wmma::load_matrix_sync(af, &bufA[(wm * 16) * ALD + ks * 16], ALD);
                wmma::load_matrix_sync(bf, &sW[(wn * 16) * WLD + ch * CHUNK + ks * 16], WLD);
                wmma::mma_sync(acc, af, bf, acc);
            }
            __syncthreads();
        }

        // Stage gates to smem
        wmma::store_matrix_sync(&sg[(wm * 16) * 36 + wn * 16], acc, 36, wmma::mem_row_major);
        __syncthreads();

        // Fused LSTM cell update (2 (b,hh) pairs per thread)
        {
            float iv0 = sg[bq * 36 + hh2]          + x0.x + sbias[hh2];
            float iv1 = sg[bq * 36 + hh2 + 1]      + x0.y + sbias[hh2 + 1];
            float fv0 = sg[bq * 36 + 8 + hh2]      + x1.x + sbias[8 + hh2];
            float fv1 = sg[bq * 36 + 8 + hh2 + 1]  + x1.y + sbias[8 + hh2 + 1];
            float gv0 = sg[bq * 36 + 16 + hh2]     + x2.x + sbias[16 + hh2];
            float gv1 = sg[bq * 36 + 16 + hh2 + 1] + x2.y + sbias[16 + hh2 + 1];
            float ov0 = sg[bq * 36 + 24 + hh2]     + x3.x + sbias[24 + hh2];
            float ov1 = sg[bq * 36 + 24 + hh2 + 1] + x3.y + sbias[24 + hh2 + 1];

            c0 = fsig(fv0) * c0 + fsig(iv0) * ftanh(gv0);
            c1 = fsig(fv1) * c1 + fsig(iv1) * ftanh(gv1);
            float h0 = fsig(ov0) * ftanh(c0);
            float h1 = fsig(ov1) * ftanh(c1);

            int hidx = nb * 8 + hh2;
            __half2 ph;
            ph.x = __float2half(h0);
            ph.y = __float2half(h1);
            *(__half2*)&g_h[wp][bq * HHH + hidx] = ph;
            if (l < 2) {
                size_t m = (size_t)bq * TT + t;
                *(__half2*)&g_in[m * HHH + hidx] = ph;
            }
            if (l == 2 && t == TT - 1) {
                g_hlast[bq * HHH + hidx]     = h0;
                g_hlast[bq * HHH + hidx + 1] = h1;
            }
        }

        // Grid barrier (skip after last step)
        if (t < TT - 1) {
            __threadfence();
            __syncthreads();
            if (tid == 0) {
                atomicAdd(&g_bar, 1u);
                unsigned want = (unsigned)(t + 1) * NBLK;
                volatile unsigned* p = &g_bar;
                while (*p < want) { }
                __threadfence();
            }
            __syncthreads();
        }
    }
}

// ----------------------------------------------------------------------------
// Final FC: out[b] = hlast[b, :] . fc_w + fc_b   (D_OUT = 1)
// ----------------------------------------------------------------------------
__global__ void fc_kernel(const float* __restrict__ fw, const float* __restrict__ fb,
                          float* __restrict__ out) {
    int b = blockIdx.x, tid = threadIdx.x;
    __shared__ float red[256];
    const float* hrow = &g_hlast[b * HHH];
    float s = 0.f;
    for (int h = tid; h < HHH; h += 256) s += hrow[h] * fw[h];
    red[tid] = s;
    __syncthreads();
    for (int off = 128; off; off >>= 1) {
        if (tid < off) red[tid] += red[tid + off];
        __syncthreads();
    }
    if (tid == 0) out[b] = red[0] + fb[0];
}

// ----------------------------------------------------------------------------
// Launch
// ----------------------------------------------------------------------------
extern "C" void kernel_launch(void* const* d_in, const int* in_sizes, int n_in,
                              void* d_out, int out_size) {
    const float* x = (const float*)d_in[0];

    cudaFuncSetAttribute(layer_kernel, cudaFuncAttributeMaxDynamicSharedMemorySize,
                         SMEM_TOTAL);

    for (int l = 0; l < 3; l++) {
        int cols = (l == 0) ? 256 : 1024;
        size_t nih = (size_t)GGG * cols;
        prep_w_kernel<<<(unsigned)((nih + 255) / 256), 256>>>(
            (const float*)d_in[1 + 4 * l], l, 0, cols);
        prep_w_kernel<<<(GGG * HHH + 255) / 256, 256>>>(
            (const float*)d_in[2 + 4 * l], l, 1, HHH);
        prep_bias_kernel<<<16, 256>>>(
            (const float*)d_in[3 + 4 * l], (const float*)d_in[4 + 4 * l], l);
    }

    split_x_kernel<<<(MTOT * 256 + 255) / 256, 256>>>(x, (size_t)MTOT * 256);

    for (int l = 0; l < 3; l++) {
        int K = (l == 0) ? 256 : 1024;
        dim3 grid(GGG / 128, MTOT / 128);
        xg_gemm_kernel<<<grid, 256>>>(l, K);
        init_state_kernel<<<256, 256>>>();
        layer_kernel<<<NBLK, NTHR, SMEM_TOTAL>>>(l);
    }
    fc_kernel<<<BATCH, 256>>>((const float*)d_in[13], (const float*)d_in[14],
                              (float*)d_out);
}